// round 1
// baseline (speedup 1.0000x reference)
#include <cuda_runtime.h>
#include <math.h>

// ---------------- problem constants ----------------
#define BB     32
#define CC     64
#define FHH    80
#define FWW    200
#define IMGH   320
#define NPTS   72
#define SPP    36      // sampled points per lane
#define LANES_ 64
#define PE_    78      // 6 + 72
#define RH_    10
#define RW_    25
#define NPOOL  250     // RH*RW
#define KDIM   2304    // SPP * CC   (k index = s*64 + c)
#define NROW   2048    // B * LANES
#define NSPLIT 12      // K splits for the fused GEMM (192 each)
#define KSPL   192

// ---------------- device scratch (no allocations allowed) ----------------
__device__ float g_xf[BB * CC * NPOOL];            // pooled features [b][c][r]
__device__ float g_W2[CC * KDIM];                  // fused conv1d+fc weight [o][s*64+c]
__device__ float g_b2[CC];                         // fused bias
__device__ float g_roi[(size_t)NROW * KDIM];       // gathered roi [n][s*64+c]
__device__ float g_xp_part[NSPLIT][NROW * CC];     // GEMM partials
__device__ float g_gv[BB * LANES_ * CC];           // attention output g

// ---------------- K1: 8x8 average pooling -> x_f ----------------
__global__ void pool_kernel(const float* __restrict__ f) {
    int bc = blockIdx.x;                 // b*64 + c
    int tid = threadIdx.x;
    __shared__ float colsum[FWW];
    const float* base = f + (size_t)bc * (FHH * FWW);
    for (int rh = 0; rh < RH_; rh++) {
        if (tid < FWW) {
            float s = 0.f;
            #pragma unroll
            for (int rr = 0; rr < 8; rr++)
                s += base[(rh * 8 + rr) * FWW + tid];
            colsum[tid] = s;
        }
        __syncthreads();
        if (tid < RW_) {
            float s = 0.f;
            #pragma unroll
            for (int q = 0; q < 8; q++) s += colsum[tid * 8 + q];
            g_xf[bc * NPOOL + rh * RW_ + tid] = s * (1.0f / 64.0f);
        }
        __syncthreads();
    }
}

// ---------------- K2: fuse conv1d + fc into W2 / b2 ----------------
// x_p[n,o] = b2[o] + sum_{c1,s} W2[o, s*64+c1] * roi[n,c1,s]
// W2[o,c1,s] = sum_{c2,k; p=s-k in [0,32)} fc_w[o, c2*32+p] * conv_w[c2,c1,k]
// b2[o] = fc_b[o] + sum_{c2} conv_b[c2] * sum_p fc_w[o, c2*32+p]
__global__ void w2_kernel(const float* __restrict__ conv_w,
                          const float* __restrict__ conv_b,
                          const float* __restrict__ fc_w,
                          const float* __restrict__ fc_b) {
    int o = blockIdx.x;
    int tid = threadIdx.x;
    __shared__ float fcrow[2048];
    __shared__ float accW[CC * SPP];     // [c1][s]
    __shared__ float bpart[CC];
    for (int i = tid; i < 2048; i += 256) fcrow[i] = fc_w[o * 2048 + i];
    for (int i = tid; i < CC * SPP; i += 256) accW[i] = 0.f;
    __syncthreads();

    int c1 = tid & 63;
    int grp = tid >> 6;                  // 4 groups of 16 c2
    float acc[SPP];
    #pragma unroll
    for (int s = 0; s < SPP; s++) acc[s] = 0.f;

    for (int c2 = grp * 16; c2 < grp * 16 + 16; c2++) {
        float w5[5];
        #pragma unroll
        for (int k = 0; k < 5; k++) w5[k] = conv_w[(c2 * CC + c1) * 5 + k];
        const float* fr = &fcrow[c2 * 32];
        #pragma unroll
        for (int s = 0; s < SPP; s++) {
            float t = 0.f;
            #pragma unroll
            for (int k = 0; k < 5; k++) {
                int p = s - k;
                if (p >= 0 && p < 32) t += w5[k] * fr[p];
            }
            acc[s] += t;
        }
    }
    #pragma unroll
    for (int s = 0; s < SPP; s++) atomicAdd(&accW[c1 * SPP + s], acc[s]);

    if (grp == 0) {      // threads 0..63, c2 = c1
        float s = 0.f;
        #pragma unroll
        for (int p = 0; p < 32; p++) s += fcrow[c1 * 32 + p];
        bpart[c1] = s * conv_b[c1];
    }
    __syncthreads();

    for (int i = tid; i < CC * SPP; i += 256) {
        int cc = i / SPP, s = i % SPP;
        g_W2[o * KDIM + s * CC + cc] = accW[i];
    }
    if (tid == 0) {
        float s = fc_b[o];
        for (int j = 0; j < CC; j++) s += bpart[j];
        g_b2[o] = s;
    }
}

// ---------------- K3: ROI gather via row staging ----------------
// block = (sp, c-quarter, b). Stage feature rows yf/yc for 16 channels in SMEM,
// then all 64 lanes read 4 corners from SMEM. Fully coalesced global traffic.
__global__ void gather_kernel(const float* __restrict__ f,
                              const float* __restrict__ prior) {
    int sp = blockIdx.x;                 // 0..35
    int cq = blockIdx.y;                 // 0..3  (16 channels each)
    int b  = blockIdx.z;                 // 0..31
    int tid = threadIdx.x;

    float yv = 0.25f * (319.0f - (320.0f / 71.0f) * (float)(2 * sp));
    yv = fminf(yv, 79.0f);
    int yc = (int)ceilf(yv);
    int yfl = (int)floorf(yv);

    __shared__ float rows[2][16][201];   // [corner(y)][c][x], padded
    __shared__ int xci[LANES_], xfi[LANES_];

    if (tid < LANES_) {
        float xv = prior[(b * LANES_ + tid) * PE_ + 6 + 2 * sp] * 0.25f;
        xv = fminf(xv, 199.0f);
        xci[tid] = (int)ceilf(xv);
        xfi[tid] = (int)floorf(xv);
    }

    const float* fb = f + (size_t)(b * CC + cq * 16) * (FHH * FWW);
    for (int i = tid; i < 2 * 16 * FWW; i += 256) {
        int j = i / (16 * FWW);
        int rem = i % (16 * FWW);
        int c = rem / FWW;
        int x = rem % FWW;
        int y = j ? yc : yfl;
        rows[j][c][x] = fb[c * (FHH * FWW) + y * FWW + x];
    }
    __syncthreads();

    for (int i = tid; i < 16 * LANES_; i += 256) {
        int c = i & 15;
        int lane = i >> 4;
        int xc_ = xci[lane], xf_ = xfi[lane];
        float v = rows[0][c][xc_] + rows[0][c][xf_] +
                  rows[1][c][xc_] + rows[1][c][xf_];
        g_roi[(size_t)(b * LANES_ + lane) * KDIM + sp * CC + cq * 16 + c] = 0.25f * v;
    }
}

// ---------------- K4: Xp = ROI(2048x2304) @ W2^T(2304x64), K-split ----------------
__global__ void gemm_kernel() {
    int mblk = blockIdx.x;               // 0..15, 128 rows each
    int spl  = blockIdx.y;               // 0..11, 192 K each
    int tid = threadIdx.x;
    int tx = tid & 15;                   // col group: 4 cols
    int ty = tid >> 4;                   // row group: 8 rows
    int row0 = mblk * 128;
    int k0 = spl * KSPL;

    __shared__ float As[128][33];
    __shared__ float Bs[64][33];

    float acc[8][4];
    #pragma unroll
    for (int i = 0; i < 8; i++)
        #pragma unroll
        for (int j = 0; j < 4; j++) acc[i][j] = 0.f;

    for (int kk = 0; kk < KSPL; kk += 32) {
        for (int i = tid; i < 128 * 32; i += 256) {
            int r = i >> 5, k = i & 31;
            As[r][k] = g_roi[(size_t)(row0 + r) * KDIM + k0 + kk + k];
        }
        for (int i = tid; i < 64 * 32; i += 256) {
            int r = i >> 5, k = i & 31;
            Bs[r][k] = g_W2[r * KDIM + k0 + kk + k];
        }
        __syncthreads();
        #pragma unroll
        for (int k = 0; k < 32; k++) {
            float a[8], bv[4];
            #pragma unroll
            for (int i = 0; i < 8; i++) a[i] = As[ty * 8 + i][k];
            #pragma unroll
            for (int j = 0; j < 4; j++) bv[j] = Bs[tx * 4 + j][k];
            #pragma unroll
            for (int i = 0; i < 8; i++)
                #pragma unroll
                for (int j = 0; j < 4; j++) acc[i][j] += a[i] * bv[j];
        }
        __syncthreads();
    }
    #pragma unroll
    for (int i = 0; i < 8; i++)
        #pragma unroll
        for (int j = 0; j < 4; j++)
            g_xp_part[spl][(row0 + ty * 8 + i) * CC + tx * 4 + j] = acc[i][j];
}

// ---------------- K5: attention (scores -> softmax -> g) ----------------
// block = (lane-quarter, b); 16 warps, one lane per warp; x_f in dyn smem.
__global__ void attn_kernel() {
    extern __shared__ float sm[];
    float* xfs = sm;                      // [64][251]
    float* xps = sm + 64 * 251;           // [16][64]
    float* wbf = xps + 16 * 64;           // [16][250]

    int lq = blockIdx.x;                  // 0..3
    int b = blockIdx.y;
    int tid = threadIdx.x;
    int w = tid >> 5, t = tid & 31;
    int lane = lq * 16 + w;
    int n = b * LANES_ + lane;

    for (int i = tid; i < CC * NPOOL; i += 512) {
        int c = i / NPOOL, r = i % NPOOL;
        xfs[c * 251 + r] = g_xf[(b * CC + c) * NPOOL + r];
    }
    // reduce GEMM partials -> x_p
    for (int o = t; o < CC; o += 32) {
        float s = g_b2[o];
        #pragma unroll
        for (int sp_ = 0; sp_ < NSPLIT; sp_++) s += g_xp_part[sp_][n * CC + o];
        xps[w * CC + o] = s;
    }
    __syncthreads();

    // scores over 250 pooled cells
    float sc[8];
    float mx = -1e30f;
    #pragma unroll
    for (int j = 0; j < 8; j++) {
        int r = t + 32 * j;
        if (r < NPOOL) {
            float s = 0.f;
            #pragma unroll 8
            for (int c = 0; c < CC; c++) s += xps[w * CC + c] * xfs[c * 251 + r];
            s *= 0.125f;                  // 1/sqrt(64)
            sc[j] = s;
            mx = fmaxf(mx, s);
        } else sc[j] = -1e30f;
    }
    #pragma unroll
    for (int off = 16; off > 0; off >>= 1)
        mx = fmaxf(mx, __shfl_xor_sync(0xffffffffu, mx, off));
    float sum = 0.f;
    #pragma unroll
    for (int j = 0; j < 8; j++) { sc[j] = __expf(sc[j] - mx); sum += sc[j]; }
    #pragma unroll
    for (int off = 16; off > 0; off >>= 1)
        sum += __shfl_xor_sync(0xffffffffu, sum, off);
    float inv = 1.0f / sum;
    #pragma unroll
    for (int j = 0; j < 8; j++) {
        int r = t + 32 * j;
        if (r < NPOOL) wbf[w * NPOOL + r] = sc[j] * inv;
    }
    __syncwarp();

    // g[c] = sum_r w[r] * xf[c][r]
    for (int c = t; c < CC; c += 32) {
        float s = 0.f;
        #pragma unroll 10
        for (int r = 0; r < NPOOL; r++) s += wbf[w * NPOOL + r] * xfs[c * 251 + r];
        g_gv[b * (LANES_ * CC) + lane * CC + c] = s;
    }
}

// ---------------- K6: conv1x1 + relu + broadcast-add prior ----------------
__global__ void final_kernel(const float* __restrict__ w1x1,
                             const float* __restrict__ b1x1,
                             const float* __restrict__ prior,
                             float* __restrict__ out) {
    int og = blockIdx.x;                  // 0..7 (8 outputs per block)
    int b = blockIdx.y;
    int tid = threadIdx.x;
    int w = tid >> 5, t = tid & 31;

    __shared__ float gvs[4096];
    __shared__ float vals[8];
    for (int i = tid; i < 4096; i += 256) gvs[i] = g_gv[b * 4096 + i];
    __syncthreads();

    int o = og * 8 + w;
    const float* wrow = w1x1 + (size_t)o * 4096;
    float s = 0.f;
    for (int j = t; j < 4096; j += 32) s += wrow[j] * gvs[j];
    #pragma unroll
    for (int off = 16; off > 0; off >>= 1)
        s += __shfl_xor_sync(0xffffffffu, s, off);
    if (t == 0) vals[w] = fmaxf(s + b1x1[o], 0.f);
    __syncthreads();

    for (int i = tid; i < 8 * PE_; i += 256) {
        int oo = i / PE_, e = i % PE_;
        int oabs = og * 8 + oo;
        int idx = b * (CC * PE_) + oabs * PE_ + e;
        out[idx] = vals[oo] + prior[idx];
    }
}

// ---------------- launch ----------------
extern "C" void kernel_launch(void* const* d_in, const int* in_sizes, int n_in,
                              void* d_out, int out_size) {
    const float* feat    = (const float*)d_in[0];
    const float* prior   = (const float*)d_in[1];
    const float* conv_w  = (const float*)d_in[2];
    const float* conv_b  = (const float*)d_in[3];
    const float* fc_w    = (const float*)d_in[4];
    const float* fc_b    = (const float*)d_in[5];
    const float* w1x1    = (const float*)d_in[6];
    const float* b1x1    = (const float*)d_in[7];
    float* out = (float*)d_out;

    const int attn_smem = (64 * 251 + 16 * 64 + 16 * 250) * (int)sizeof(float);
    cudaFuncSetAttribute(attn_kernel, cudaFuncAttributeMaxDynamicSharedMemorySize,
                         attn_smem);

    pool_kernel<<<BB * CC, 256>>>(feat);
    w2_kernel<<<CC, 256>>>(conv_w, conv_b, fc_w, fc_b);
    gather_kernel<<<dim3(SPP, 4, BB), 256>>>(feat, prior);
    gemm_kernel<<<dim3(16, NSPLIT), 256>>>();
    attn_kernel<<<dim3(4, BB), 512, attn_smem>>>();
    final_kernel<<<dim3(8, BB), 256>>>(w1x1, b1x1, prior, out);
}